// round 4
// baseline (speedup 1.0000x reference)
#include <cuda_runtime.h>

// JPEG compression differentiable-round pipeline, fully fused single kernel.
// Layout: image [32, 3, 512, 512] f32, output identical.
// CTA = 256 threads handles one 32x32 pixel tile of one batch image:
//   phase A: coalesced float4 streaming loads of R,G,B -> YCbCr; Y to smem;
//            Cb/Cr 2x2-mean downsampled on the fly via register pair-sums +
//            __shfl_down_sync(8) (row pairs always land in one warp),
//            written directly to 16x16 smem planes.
//   phase C: 8x8 DCT -> diff-round quant -> IDCT, in-place in smem.
//            16 Y blocks (warps 0-3), 4 Cb blocks (warp 4), 4 Cr blocks
//            (warp 5); warps 6-7 idle for this phase. Each participating
//            thread owns one 8-element block-row; transposes via smem +
//            __syncwarp (a block never spans a warp).
//   phase D: chroma upsample + YCbCr->RGB + clip, streaming float4 stores.

#define HW 512
#define PLANE (512 * 512)

__constant__ int YTAB[64] = {
    16, 11, 10, 16, 24, 40, 51, 61,
    12, 12, 14, 19, 26, 58, 60, 55,
    14, 13, 16, 24, 40, 57, 69, 56,
    14, 17, 22, 29, 51, 87, 80, 62,
    18, 22, 37, 56, 68, 109, 103, 77,
    24, 35, 55, 64, 81, 104, 113, 92,
    49, 64, 78, 87, 103, 121, 120, 101,
    72, 92, 95, 98, 112, 100, 103, 99};

__constant__ int CTAB[64] = {
    17, 18, 24, 47, 99, 99, 99, 99,
    18, 21, 26, 66, 99, 99, 99, 99,
    24, 26, 56, 99, 99, 99, 99, 99,
    47, 66, 99, 99, 99, 99, 99, 99,
    99, 99, 99, 99, 99, 99, 99, 99,
    99, 99, 99, 99, 99, 99, 99, 99,
    99, 99, 99, 99, 99, 99, 99, 99,
    99, 99, 99, 99, 99, 99, 99, 99};

// QUALITY = 80 -> FACTOR = (200 - 160) / 100 = 0.4
#define QFACTOR 0.4f

__global__ void __launch_bounds__(256)
jpeg_kernel(const float* __restrict__ in, float* __restrict__ out)
{
    __shared__ float ys[32 * 33];   // Y tile (stride 33 = conflict-free)
    __shared__ float cbs[16 * 17];  // downsampled Cb (stride 17)
    __shared__ float crs[16 * 17];  // downsampled Cr
    __shared__ float Dm[64];        // orthonormal DCT matrix D[u][x]
    __shared__ float qY[64], rqY[64], qC[64], rqC[64];

    const int tid = threadIdx.x;

    // ---- table init (overlaps with global loads below) ----
    if (tid < 64) {
        int u = tid >> 3, x = tid & 7;
        float a = (u == 0) ? 0.7071067811865476f : 1.0f;
        Dm[tid] = 0.5f * a * cospif((float)((2 * x + 1) * u) * (1.0f / 16.0f));
        float qy = (float)YTAB[tid] * QFACTOR;
        float qc = (float)CTAB[tid] * QFACTOR;
        qY[tid] = qy;  rqY[tid] = 1.0f / qy;
        qC[tid] = qc;  rqC[tid] = 1.0f / qc;
    }

    // ---- phase A: load RGB, convert to YCbCr, downsample chroma in regs ----
    const int b   = blockIdx.z;
    const int gy0 = blockIdx.y * 32;
    const int gx0 = blockIdx.x * 32;
    const int row = tid >> 3;          // 0..31
    const int col = (tid & 7) << 2;    // 0,4,...,28

    const float* pR = in + (size_t)b * 3 * PLANE;
    const float* pG = pR + PLANE;
    const float* pB = pG + PLANE;
    const size_t off = (size_t)(gy0 + row) * HW + gx0 + col;

    // streaming loads: data is read exactly once chip-wide -> evict-first
    float4 r4 = __ldcs((const float4*)(pR + off));
    float4 g4 = __ldcs((const float4*)(pG + off));
    float4 b4 = __ldcs((const float4*)(pB + off));

    float cbv[4], crv[4];
    #pragma unroll
    for (int i = 0; i < 4; i++) {
        float R = (&r4.x)[i] * 255.0f;
        float G = (&g4.x)[i] * 255.0f;
        float B = (&b4.x)[i] * 255.0f;
        float y  =  0.299f    * R + 0.587f    * G + 0.114f    * B;
        cbv[i]   = -0.168736f * R - 0.331264f * G + 0.5f      * B + 128.0f;
        crv[i]   =  0.5f      * R - 0.418688f * G - 0.081312f * B + 128.0f;
        ys[row * 33 + col + i] = y;
    }

    // horizontal pair sums in registers
    float hb0 = cbv[0] + cbv[1], hb1 = cbv[2] + cbv[3];
    float hr0 = crv[0] + crv[1], hr1 = crv[2] + crv[3];
    // vertical: partner thread is tid+8 (row+1, same cols) — always same warp,
    // since each warp owns 4 aligned rows and pairs are (even,odd).
    float vb0 = hb0 + __shfl_down_sync(0xffffffffu, hb0, 8);
    float vb1 = hb1 + __shfl_down_sync(0xffffffffu, hb1, 8);
    float vr0 = hr0 + __shfl_down_sync(0xffffffffu, hr0, 8);
    float vr1 = hr1 + __shfl_down_sync(0xffffffffu, hr1, 8);
    if ((tid & 8) == 0) {              // even rows write 2 downsampled values
        int dr = row >> 1;             // 0..15
        int dc = (tid & 7) << 1;       // 0,2,...,14
        cbs[dr * 17 + dc]     = 0.25f * vb0;
        cbs[dr * 17 + dc + 1] = 0.25f * vb1;
        crs[dr * 17 + dc]     = 0.25f * vr0;
        crs[dr * 17 + dc + 1] = 0.25f * vr1;
    }
    __syncthreads();

    // ---- phase C: per-block DCT -> diff-round quant -> IDCT, in place ----
    // 16 Y blocks -> warps 0-3 (128 threads)
    //  4 Cb blocks -> warp 4 (32 threads)
    //  4 Cr blocks -> warp 5 (32 threads)
    // warps 6-7 skip this phase.
    const int warp = tid >> 5;
    if (warp < 6) {
        const int lane = tid & 7;        // row within the 8x8 block
        float* base;
        int stride;
        const float* q;
        const float* rq;

        if (warp < 4) {                  // 16 Y blocks: tid 0..127
            int blk = tid >> 3;          // 0..15
            base = ys + (blk >> 2) * 8 * 33 + (blk & 3) * 8;
            stride = 33; q = qY; rq = rqY;
        } else if (warp == 4) {          // 4 Cb blocks: tid 128..159
            int blk = (tid - 128) >> 3;  // 0..3
            base = cbs + (blk >> 1) * 8 * 17 + (blk & 1) * 8;
            stride = 17; q = qC; rq = rqC;
        } else {                         // 4 Cr blocks: tid 160..191
            int blk = (tid - 160) >> 3;  // 0..3
            base = crs + (blk >> 1) * 8 * 17 + (blk & 1) * 8;
            stride = 17; q = qC; rq = rqC;
        }

        // stage 1: row transform  G[x][v] = sum_y (X[x][y]-128) * D[v][y]
        float xr[8], t[8];
        #pragma unroll
        for (int y = 0; y < 8; y++) xr[y] = base[lane * stride + y] - 128.0f;
        #pragma unroll
        for (int v = 0; v < 8; v++) {
            float s = 0.0f;
            #pragma unroll
            for (int y = 0; y < 8; y++) s += xr[y] * Dm[v * 8 + y];
            t[v] = s;
        }
        #pragma unroll
        for (int v = 0; v < 8; v++) base[lane * stride + v] = t[v];
        __syncwarp();

        // stage 2: column transform  coef[u=lane][v] = sum_k D[lane][k] * G[k][v]
        float c[8];
        #pragma unroll
        for (int v = 0; v < 8; v++) c[v] = 0.0f;
        #pragma unroll
        for (int k = 0; k < 8; k++) {
            float dk = Dm[lane * 8 + k];
            #pragma unroll
            for (int v = 0; v < 8; v++) c[v] += dk * base[k * stride + v];
        }

        // quant: diff_round(coef/q) * q,  diff_round(x) = r + (x-r)^3
        #pragma unroll
        for (int v = 0; v < 8; v++) {
            float cf = c[v] * rq[lane * 8 + v];
            float r  = rintf(cf);
            float d  = cf - r;
            c[v] = (r + d * d * d) * q[lane * 8 + v];
        }

        // stage 3: P[lane][y] = sum_v coef[lane][v] * D[v][y]  (registers)
        #pragma unroll
        for (int y = 0; y < 8; y++) {
            float s = 0.0f;
            #pragma unroll
            for (int v = 0; v < 8; v++) s += c[v] * Dm[v * 8 + y];
            t[y] = s;
        }
        __syncwarp();   // all reads of G done before overwriting with P
        #pragma unroll
        for (int y = 0; y < 8; y++) base[lane * stride + y] = t[y];
        __syncwarp();

        // stage 4: out[x=lane][y] = sum_u D[u][lane] * P[u][y] + 128
        float o[8];
        #pragma unroll
        for (int y = 0; y < 8; y++) o[y] = 128.0f;
        #pragma unroll
        for (int u = 0; u < 8; u++) {
            float du = Dm[u * 8 + lane];
            #pragma unroll
            for (int y = 0; y < 8; y++) o[y] += du * base[u * stride + y];
        }
        __syncwarp();   // all reads of P done before overwriting with result
        #pragma unroll
        for (int y = 0; y < 8; y++) base[lane * stride + y] = o[y];
    }
    __syncthreads();

    // ---- phase D: upsample chroma, YCbCr->RGB, clip, store ----
    {
        float4 ro, go, bo;
        #pragma unroll
        for (int i = 0; i < 4; i++) {
            int cc = col + i;
            float y  = ys[row * 33 + cc];
            int ci = (row >> 1) * 17 + (cc >> 1);
            float cb = cbs[ci] - 128.0f;
            float cr = crs[ci] - 128.0f;
            float R = y + 1.402f * cr;
            float G = y - 0.344136f * cb - 0.714136f * cr;
            float B = y + 1.772f * cb;
            (&ro.x)[i] = fminf(fmaxf(R, 0.0f), 255.0f) * (1.0f / 255.0f);
            (&go.x)[i] = fminf(fmaxf(G, 0.0f), 255.0f) * (1.0f / 255.0f);
            (&bo.x)[i] = fminf(fmaxf(B, 0.0f), 255.0f) * (1.0f / 255.0f);
        }
        float* oR = out + (size_t)b * 3 * PLANE;
        float* oG = oR + PLANE;
        float* oB = oG + PLANE;
        __stcs((float4*)(oR + off), ro);
        __stcs((float4*)(oG + off), go);
        __stcs((float4*)(oB + off), bo);
    }
}

extern "C" void kernel_launch(void* const* d_in, const int* in_sizes, int n_in,
                              void* d_out, int out_size)
{
    const float* in = (const float*)d_in[0];
    float* out = (float*)d_out;
    dim3 grid(HW / 32, HW / 32, 32);   // (16, 16, 32) tiles
    jpeg_kernel<<<grid, 256>>>(in, out);
}

// round 6
// speedup vs baseline: 1.4325x; 1.4325x over previous
#include <cuda_runtime.h>

// JPEG compression differentiable-round pipeline, fully fused single kernel.
// Phase C restructured so the DCT matrix is consumed ONLY with
// compile-time indices -> fp32 immediates in FFMA (no smem/const traffic),
// and each thread owns a block COLUMN in the middle stages (reads 8 values
// instead of re-reading the whole 8x8 block). Shared-mem ops in phase C drop
// from ~300 LDS/thread to 40 LDS + 24 STS. Two of four __syncwarp removed
// (own-address transposes). ys padded to stride 36 for float4 smem ops.

#define HW 512
#define PLANE (512 * 512)
#define YSTR 36   // Y tile smem row stride (floats): 16B-aligned rows, odd bank step
#define CSTR 17   // chroma tile stride

// Orthonormal 8x8 DCT-II matrix D[u][x] = 0.5*alpha_u*cos((2x+1)u*pi/16).
// Compile-time constants -> folded into FFMA immediates after unrolling.
__device__ constexpr float DC[64] = {
    0.35355339059327373f,  0.35355339059327373f,  0.35355339059327373f,  0.35355339059327373f,
    0.35355339059327373f,  0.35355339059327373f,  0.35355339059327373f,  0.35355339059327373f,
    0.49039264020161522f,  0.41573480615127262f,  0.27778511650980114f,  0.09754516100806417f,
   -0.09754516100806417f, -0.27778511650980114f, -0.41573480615127262f, -0.49039264020161522f,
    0.46193976625564337f,  0.19134171618254492f, -0.19134171618254492f, -0.46193976625564337f,
   -0.46193976625564337f, -0.19134171618254492f,  0.19134171618254492f,  0.46193976625564337f,
    0.41573480615127262f, -0.09754516100806417f, -0.49039264020161522f, -0.27778511650980114f,
    0.27778511650980114f,  0.49039264020161522f,  0.09754516100806417f, -0.41573480615127262f,
    0.35355339059327373f, -0.35355339059327373f, -0.35355339059327373f,  0.35355339059327373f,
    0.35355339059327373f, -0.35355339059327373f, -0.35355339059327373f,  0.35355339059327373f,
    0.27778511650980114f, -0.49039264020161522f,  0.09754516100806417f,  0.41573480615127262f,
   -0.41573480615127262f, -0.09754516100806417f,  0.49039264020161522f, -0.27778511650980114f,
    0.19134171618254492f, -0.46193976625564337f,  0.46193976625564337f, -0.19134171618254492f,
   -0.19134171618254492f,  0.46193976625564337f, -0.46193976625564337f,  0.19134171618254492f,
    0.09754516100806417f, -0.27778511650980114f,  0.41573480615127262f, -0.49039264020161522f,
    0.49039264020161522f, -0.41573480615127262f,  0.27778511650980114f, -0.09754516100806417f};

__constant__ int YTAB[64] = {
    16, 11, 10, 16, 24, 40, 51, 61,
    12, 12, 14, 19, 26, 58, 60, 55,
    14, 13, 16, 24, 40, 57, 69, 56,
    14, 17, 22, 29, 51, 87, 80, 62,
    18, 22, 37, 56, 68, 109, 103, 77,
    24, 35, 55, 64, 81, 104, 113, 92,
    49, 64, 78, 87, 103, 121, 120, 101,
    72, 92, 95, 98, 112, 100, 103, 99};

__constant__ int CTAB[64] = {
    17, 18, 24, 47, 99, 99, 99, 99,
    18, 21, 26, 66, 99, 99, 99, 99,
    24, 26, 56, 99, 99, 99, 99, 99,
    47, 66, 99, 99, 99, 99, 99, 99,
    99, 99, 99, 99, 99, 99, 99, 99,
    99, 99, 99, 99, 99, 99, 99, 99,
    99, 99, 99, 99, 99, 99, 99, 99,
    99, 99, 99, 99, 99, 99, 99, 99};

// QUALITY = 80 -> FACTOR = (200 - 160) / 100 = 0.4
#define QFACTOR 0.4f

__global__ void __launch_bounds__(256)
jpeg_kernel(const float* __restrict__ in, float* __restrict__ out)
{
    __shared__ __align__(16) float ys[32 * YSTR];   // Y tile
    __shared__ float cbs[16 * CSTR];                // downsampled Cb
    __shared__ float crs[16 * CSTR];                // downsampled Cr
    __shared__ float qY[64], rqY[64], qC[64], rqC[64];

    const int tid = threadIdx.x;

    // ---- quant table init (overlaps with global loads) ----
    if (tid < 64) {
        float qy = (float)YTAB[tid] * QFACTOR;
        float qc = (float)CTAB[tid] * QFACTOR;
        qY[tid] = qy;  rqY[tid] = 1.0f / qy;
        qC[tid] = qc;  rqC[tid] = 1.0f / qc;
    }

    // ---- phase A: load RGB, convert to YCbCr, downsample chroma in regs ----
    const int b   = blockIdx.z;
    const int gy0 = blockIdx.y * 32;
    const int gx0 = blockIdx.x * 32;
    const int row = tid >> 3;          // 0..31
    const int col = (tid & 7) << 2;    // 0,4,...,28

    const float* pR = in + (size_t)b * 3 * PLANE;
    const float* pG = pR + PLANE;
    const float* pB = pG + PLANE;
    const size_t off = (size_t)(gy0 + row) * HW + gx0 + col;

    // streaming loads: data is read exactly once chip-wide -> evict-first
    float4 r4 = __ldcs((const float4*)(pR + off));
    float4 g4 = __ldcs((const float4*)(pG + off));
    float4 b4 = __ldcs((const float4*)(pB + off));

    float4 y4;
    float cbv[4], crv[4];
    #pragma unroll
    for (int i = 0; i < 4; i++) {
        float R = (&r4.x)[i] * 255.0f;
        float G = (&g4.x)[i] * 255.0f;
        float B = (&b4.x)[i] * 255.0f;
        (&y4.x)[i] =  0.299f    * R + 0.587f    * G + 0.114f    * B;
        cbv[i]     = -0.168736f * R - 0.331264f * G + 0.5f      * B + 128.0f;
        crv[i]     =  0.5f      * R - 0.418688f * G - 0.081312f * B + 128.0f;
    }
    *(float4*)&ys[row * YSTR + col] = y4;

    // chroma 2x2 mean: horizontal pair sums in regs, vertical via shuffle
    float hb0 = cbv[0] + cbv[1], hb1 = cbv[2] + cbv[3];
    float hr0 = crv[0] + crv[1], hr1 = crv[2] + crv[3];
    // partner thread is tid+8 (row+1, same cols) — always same warp.
    float vb0 = hb0 + __shfl_down_sync(0xffffffffu, hb0, 8);
    float vb1 = hb1 + __shfl_down_sync(0xffffffffu, hb1, 8);
    float vr0 = hr0 + __shfl_down_sync(0xffffffffu, hr0, 8);
    float vr1 = hr1 + __shfl_down_sync(0xffffffffu, hr1, 8);
    if ((tid & 8) == 0) {              // even rows write 2 downsampled values
        int dr = row >> 1;             // 0..15
        int dc = (tid & 7) << 1;       // 0,2,...,14
        cbs[dr * CSTR + dc]     = 0.25f * vb0;
        cbs[dr * CSTR + dc + 1] = 0.25f * vb1;
        crs[dr * CSTR + dc]     = 0.25f * vr0;
        crs[dr * CSTR + dc + 1] = 0.25f * vr1;
    }
    __syncthreads();

    // ---- phase C: per-block DCT -> diff-round quant -> IDCT, in place ----
    // 16 Y blocks -> warps 0-3; 4 Cb -> warp 4; 4 Cr -> warp 5; 6-7 idle.
    // Thread owns block ROW `lane` in stages 1/4 and block COLUMN `lane`
    // in stages 2/3; D matrix is immediate-folded, never loaded.
    const int warp = tid >> 5;
    if (warp < 6) {
        const int lane = tid & 7;
        float* base;
        int stride;
        const float* q;
        const float* rq;

        if (warp < 4) {                  // 16 Y blocks: tid 0..127
            int blk = tid >> 3;          // 0..15
            base = ys + (blk >> 2) * 8 * YSTR + (blk & 3) * 8;
            stride = YSTR; q = qY; rq = rqY;
        } else if (warp == 4) {          // 4 Cb blocks: tid 128..159
            int blk = (tid - 128) >> 3;  // 0..3
            base = cbs + (blk >> 1) * 8 * CSTR + (blk & 1) * 8;
            stride = CSTR; q = qC; rq = rqC;
        } else {                         // 4 Cr blocks: tid 160..191
            int blk = (tid - 160) >> 3;  // 0..3
            base = crs + (blk >> 1) * 8 * CSTR + (blk & 1) * 8;
            stride = CSTR; q = qC; rq = rqC;
        }

        // stage 1 (row transform): thread owns row x=lane.
        // G[x][v] = sum_y (X[x][y]-128) * D[v][y]   (D = immediates)
        float xr[8], g[8];
        #pragma unroll
        for (int y = 0; y < 8; y++) xr[y] = base[lane * stride + y] - 128.0f;
        #pragma unroll
        for (int v = 0; v < 8; v++) {
            float s = 0.0f;
            #pragma unroll
            for (int y = 0; y < 8; y++) s += xr[y] * DC[v * 8 + y];
            g[v] = s;
        }
        #pragma unroll
        for (int v = 0; v < 8; v++) base[lane * stride + v] = g[v];
        __syncwarp();   // all G rows visible before column reads

        // stage 2 (column transform): thread owns column v=lane.
        // coef[u][lane] = sum_k D[u][k] * G[k][lane]
        float gc[8];
        #pragma unroll
        for (int k = 0; k < 8; k++) gc[k] = base[k * stride + lane];
        float c[8];
        #pragma unroll
        for (int u = 0; u < 8; u++) {
            float s = 0.0f;
            #pragma unroll
            for (int k = 0; k < 8; k++) s += gc[k] * DC[u * 8 + k];
            c[u] = s;
        }

        // quant on column lane: q index = u*8 + lane
        #pragma unroll
        for (int u = 0; u < 8; u++) {
            float cf = c[u] * rq[u * 8 + lane];
            float r  = rintf(cf);
            float d  = cf - r;
            c[u] = (r + d * d * d) * q[u * 8 + lane];
        }

        // stage 3 (IDCT first half, registers only):
        // T[x][lane] = sum_u D[u][x] * coef[u][lane]
        float t[8];
        #pragma unroll
        for (int x = 0; x < 8; x++) {
            float s = 0.0f;
            #pragma unroll
            for (int u = 0; u < 8; u++) s += c[u] * DC[u * 8 + x];
            t[x] = s;
        }
        // write T column lane — same addresses this thread alone read in
        // stage 2, so no barrier needed before the overwrite.
        #pragma unroll
        for (int x = 0; x < 8; x++) base[x * stride + lane] = t[x];
        __syncwarp();   // all T columns visible before row reads

        // stage 4 (IDCT second half): thread owns row x=lane.
        // out[lane][y] = 128 + sum_v T[lane][v] * D[v][y]
        float tr[8];
        #pragma unroll
        for (int v = 0; v < 8; v++) tr[v] = base[lane * stride + v];
        #pragma unroll
        for (int y = 0; y < 8; y++) {
            float s = 128.0f;
            #pragma unroll
            for (int v = 0; v < 8; v++) s += tr[v] * DC[v * 8 + y];
            base[lane * stride + y] = s;   // own row: no hazard
        }
    }
    __syncthreads();

    // ---- phase D: upsample chroma, YCbCr->RGB, clip, store ----
    {
        float4 yv = *(const float4*)&ys[row * YSTR + col];
        float4 ro, go, bo;
        #pragma unroll
        for (int i = 0; i < 4; i++) {
            int cc = col + i;
            float y  = (&yv.x)[i];
            int ci = (row >> 1) * CSTR + (cc >> 1);
            float cb = cbs[ci] - 128.0f;
            float cr = crs[ci] - 128.0f;
            float R = y + 1.402f * cr;
            float G = y - 0.344136f * cb - 0.714136f * cr;
            float B = y + 1.772f * cb;
            (&ro.x)[i] = fminf(fmaxf(R, 0.0f), 255.0f) * (1.0f / 255.0f);
            (&go.x)[i] = fminf(fmaxf(G, 0.0f), 255.0f) * (1.0f / 255.0f);
            (&bo.x)[i] = fminf(fmaxf(B, 0.0f), 255.0f) * (1.0f / 255.0f);
        }
        float* oR = out + (size_t)b * 3 * PLANE;
        float* oG = oR + PLANE;
        float* oB = oG + PLANE;
        __stcs((float4*)(oR + off), ro);
        __stcs((float4*)(oG + off), go);
        __stcs((float4*)(oB + off), bo);
    }
}

extern "C" void kernel_launch(void* const* d_in, const int* in_sizes, int n_in,
                              void* d_out, int out_size)
{
    const float* in = (const float*)d_in[0];
    float* out = (float*)d_out;
    dim3 grid(HW / 32, HW / 32, 32);   // (16, 16, 32) tiles
    jpeg_kernel<<<grid, 256>>>(in, out);
}